// round 8
// baseline (speedup 1.0000x reference)
#include <cuda_runtime.h>
#include <cuda_fp16.h>
#include <cstdint>

// Problem constants
#define MM 32
#define KK 8192
#define NN 8192
#define GROUP 128

// Tiling
#define K_SPLIT 8
#define K_CHUNK (KK / K_SPLIT)           // 1024
#define GROUPS_PER_CTA (K_CHUNK / GROUP) // 8
#define WARPS 4
#define THREADS 128
#define WARP_N 32
#define N_TILE (WARPS * WARP_N)          // 128
#define NTILES (NN / N_TILE)             // 64
#define ASTRIDE 136                      // fp16 elems per SMEM A row (128 + 8 pad)

// Deterministic K-split partials + split-K arrival counters (no atomic-float, no alloc)
__device__ __align__(16) float  g_scratch[K_SPLIT * MM * NN]; // 8 MB
__device__ unsigned int g_cnt[NTILES];                        // zero-init; reset by last CTA

// ---------------- PTX helpers ----------------
__device__ __forceinline__ void ldsm_x4(uint32_t addr, uint32_t* r) {
    asm volatile("ldmatrix.sync.aligned.m8n8.x4.shared.b16 {%0,%1,%2,%3}, [%4];"
                 : "=r"(r[0]), "=r"(r[1]), "=r"(r[2]), "=r"(r[3]) : "r"(addr));
}

__device__ __forceinline__ void lds128(uint32_t addr, uint32_t* r) {
    asm volatile("ld.shared.v4.u32 {%0,%1,%2,%3}, [%4];"
                 : "=r"(r[0]), "=r"(r[1]), "=r"(r[2]), "=r"(r[3]) : "r"(addr));
}

__device__ __forceinline__ void mma16816(float* c, const uint32_t* a, uint32_t b0, uint32_t b1) {
    asm volatile("mma.sync.aligned.m16n8k16.row.col.f32.f16.f16.f32 "
                 "{%0,%1,%2,%3}, {%4,%5,%6,%7}, {%8,%9}, {%0,%1,%2,%3};"
                 : "+f"(c[0]), "+f"(c[1]), "+f"(c[2]), "+f"(c[3])
                 : "r"(a[0]), "r"(a[1]), "r"(a[2]), "r"(a[3]), "r"(b0), "r"(b1));
}

// Extract byte (two int4 k-values) selected by psel, produce fp16x2 = (q_lo-8, q_hi-8) exactly.
// 1024+q is exact in fp16 (ulp=1 at 2^10): 0x6400 | q. 1032.0f16 = 0x6408 (exact).
__device__ __forceinline__ uint32_t dqh(uint32_t w, uint32_t psel) {
    uint32_t v;
    asm("prmt.b32 %0, %1, 0, %2;" : "=r"(v) : "r"(w), "r"(psel)); // clean byte -> byte0
    uint32_t t = ((v | (v << 12)) & 0x000F000Fu) | 0x64006400u;   // fp16x2(1024+q)
    __half2 x = *reinterpret_cast<__half2*>(&t);
    const __half2 c = __half2half2(__ushort_as_half(0x6408));     // 1032.0
    __half2 y = __hsub2(x, c);                                    // exact: q-8 in [-8,7]
    return *reinterpret_cast<uint32_t*>(&y);
}

__device__ __forceinline__ void cp16(uint32_t saddr, const void* gptr) {
    asm volatile("cp.async.cg.shared.global [%0], [%1], 16;" :: "r"(saddr), "l"(gptr));
}
__device__ __forceinline__ void cp4(uint32_t saddr, const void* gptr) {
    asm volatile("cp.async.ca.shared.global [%0], [%1], 4;" :: "r"(saddr), "l"(gptr));
}
__device__ __forceinline__ void cp_commit() {
    asm volatile("cp.async.commit_group;");
}
template <int N>
__device__ __forceinline__ void cp_wait() {
    asm volatile("cp.async.wait_group %0;" :: "n"(N));
}

// ---------------- Fused GEMM (convert + mma + split-K reduce) ----------------
// SMEM:
//   sa32: one group of A as fp32 [32 x 128]                 (16 KB, single buffer)
//   sa16: one group of A as fp16 [32 x ASTRIDE]             (8.5 KB, single buffer)
//   sq:   permuted qweight tiles, double-buffered           (16 KB)
// sq layout per buffer (2048 words): off = ks*256 + warp*64 + lq*8 + rl*4 + nf
__global__ void __launch_bounds__(THREADS, 4)
marlin_fused_kernel(const float* __restrict__ A,
                    const int*   __restrict__ qweight,
                    const float* __restrict__ scales,
                    const float* __restrict__ bias,
                    float*       __restrict__ out) {
    __shared__ __align__(16) float  sa32[MM * 128];
    __shared__ __align__(16) __half sa16[MM * ASTRIDE];
    __shared__ __align__(16) int    sq[2][2048];
    __shared__ unsigned int s_last;

    const int tid  = threadIdx.x;
    const int warp = tid >> 5;
    const int lane = tid & 31;
    const int lq   = lane >> 2;   // 0..7
    const int lr   = lane & 3;    // 0..3
    const uint32_t psel = 0x4440u | (uint32_t)lr;  // PRMT: pick byte lr

    const int nb_cta = blockIdx.x * N_TILE;
    const int nb     = nb_cta + warp * WARP_N;
    const int kbase  = blockIdx.y * K_CHUNK;

    const int lm_row = lane & 15;
    const int lm_k   = (lane >> 4) << 3;

    const uint32_t sa32_base = (uint32_t)__cvta_generic_to_shared(&sa32[0]);
    const uint32_t sa16_base = (uint32_t)__cvta_generic_to_shared(&sa16[0]);
    const uint32_t sq_base   = (uint32_t)__cvta_generic_to_shared(&sq[0][0]);

    // Permuted qweight destination pieces that depend only on tid:
    const int perm_c = ((tid >> 5) << 6) | ((tid & 7) << 3) | ((tid >> 3) & 3);

    // ---- async stage of one group's fp32 A ----
    auto stage_a = [&](int gk) {
#pragma unroll
        for (int it = 0; it < 8; it++) {
            const int i   = it * THREADS + tid;     // 0..1023 granules of 16B
            const int row = i >> 5, c = i & 31;     // 32 rows x 32 granules
            cp16(sa32_base + (uint32_t)(row * 512 + c * 16),
                 A + (size_t)row * KK + gk + c * 4);
        }
    };
    // ---- async stage of one group's permuted qweight tile ----
    auto stage_q = [&](int buf, int gk) {
        const uint32_t sq_b = sq_base + (uint32_t)buf * (2048 * 4);
        const int kp_g = gk >> 3;
        const int* qsrc = qweight + (size_t)kp_g * NN + nb_cta + tid;
#pragma unroll
        for (int r = 0; r < 16; r++) {
            const int ks = r >> 1, rl = r & 1;
            const int off = ks * 256 + perm_c + rl * 4;
            cp4(sq_b + (uint32_t)off * 4, qsrc + (size_t)r * NN);
        }
    };

    float acc[32];
#pragma unroll
    for (int i = 0; i < 32; i++) acc[i] = 0.f;

    stage_a(kbase);
    stage_q(0, kbase);
    cp_commit();

    for (int g = 0; g < GROUPS_PER_CTA; g++) {
        const int gk = kbase + g * GROUP;
        cp_wait<0>();
        __syncthreads();   // staged data visible; prior group's sa16/sq reads done

        // Convert this group's A: sa32 (fp32) -> sa16 (fp16), conflict-free
#pragma unroll
        for (int it = 0; it < 8; it++) {
            const int f   = it * THREADS + tid;     // float4 index 0..1023
            const int row = f >> 5, c4 = f & 31;
            const float4 v = reinterpret_cast<const float4*>(sa32)[f];
            __half2 h0 = __floats2half2_rn(v.x, v.y);
            __half2 h1 = __floats2half2_rn(v.z, v.w);
            uint2 o;
            o.x = *reinterpret_cast<uint32_t*>(&h0);
            o.y = *reinterpret_cast<uint32_t*>(&h1);
            *reinterpret_cast<uint2*>(&sa16[row * ASTRIDE + c4 * 4]) = o;
        }
        __syncthreads();   // sa16 ready; sa32 free for restage

        if (g + 1 < GROUPS_PER_CTA) {
            stage_a(gk + GROUP);
            stage_q((g + 1) & 1, gk + GROUP);
            cp_commit();
        }

        // Prefetch this group's scales (consumed after the mma loop)
        const float* sp = scales + (size_t)(gk >> 7) * NN + nb + (lr << 1);
        float s[8];
#pragma unroll
        for (int nf = 0; nf < 4; nf++) {
            s[2 * nf]     = __ldg(sp + nf * 8);
            s[2 * nf + 1] = __ldg(sp + nf * 8 + 1);
        }

        float pc[32];
#pragma unroll
        for (int i = 0; i < 32; i++) pc[i] = 0.f;

        const uint32_t sq_b = sq_base + (uint32_t)(g & 1) * (2048 * 4)
                            + (uint32_t)(warp * 64 + lq * 8) * 4;

#pragma unroll
        for (int ks = 0; ks < 8; ks++) {
            uint32_t a0[4], a1[4];
            const int kcol = (ks << 4) + lm_k;
            ldsm_x4(sa16_base + (uint32_t)(lm_row * ASTRIDE + kcol) * 2, a0);
            ldsm_x4(sa16_base + (uint32_t)((16 + lm_row) * ASTRIDE + kcol) * 2, a1);

            uint32_t q[8];
            const uint32_t qaddr = sq_b + (uint32_t)(ks * 256) * 4;
            lds128(qaddr, q);          // k 0-7,  nf 0..3
            lds128(qaddr + 16, q + 4); // k 8-15, nf 0..3

            uint32_t b0[4], b1[4];
#pragma unroll
            for (int nf = 0; nf < 4; nf++) {
                b0[nf] = dqh(q[nf], psel);
                b1[nf] = dqh(q[4 + nf], psel);
            }
#pragma unroll
            for (int nf = 0; nf < 4; nf++) {
                mma16816(pc + nf * 8,     a0, b0[nf], b1[nf]);
                mma16816(pc + nf * 8 + 4, a1, b0[nf], b1[nf]);
            }
        }

        // Apply per-(group, n) fp32 scales in registers
#pragma unroll
        for (int nf = 0; nf < 4; nf++) {
            const float s0 = s[2 * nf], s1 = s[2 * nf + 1];
            float* p = pc + nf * 8;
            float* a = acc + nf * 8;
            a[0] += p[0] * s0; a[1] += p[1] * s1; a[2] += p[2] * s0; a[3] += p[3] * s1;
            a[4] += p[4] * s0; a[5] += p[5] * s1; a[6] += p[6] * s0; a[7] += p[7] * s1;
        }
        // (next iteration's top __syncthreads protects sa16/sq reuse)
    }

    // ---- Deterministic K-split partials ----
    float* dst = g_scratch + (size_t)blockIdx.y * (MM * NN);
#pragma unroll
    for (int nf = 0; nf < 4; nf++) {
#pragma unroll
        for (int mt = 0; mt < 2; mt++) {
            const float* c = acc + nf * 8 + mt * 4;
            const int col  = nb + nf * 8 + (lr << 1);
            const int row0 = mt * 16 + lq;
            *reinterpret_cast<float2*>(dst + (size_t)row0 * NN + col)       = make_float2(c[0], c[1]);
            *reinterpret_cast<float2*>(dst + (size_t)(row0 + 8) * NN + col) = make_float2(c[2], c[3]);
        }
    }

    // ---- Fused split-K reduction: last-arriving CTA of this n-tile finishes ----
    __threadfence();       // partials visible before the arrival tick
    __syncthreads();       // all threads' partial stores issued before tid0 ticks
    if (tid == 0) {
        const unsigned old = atomicAdd(&g_cnt[blockIdx.x], 1u);
        if (old == K_SPLIT - 1) {
            g_cnt[blockIdx.x] = 0;   // reset for next launch (graph replay safe)
            s_last = 1u;
        } else {
            s_last = 0u;
        }
    }
    __syncthreads();

    if (s_last) {
        __threadfence();   // acquire: see all other CTAs' partials
#pragma unroll
        for (int it = 0; it < 8; it++) {
            const int f   = it * THREADS + tid;     // float4 index within tile
            const int row = f >> 5, c4 = f & 31;
            const int col = nb_cta + c4 * 4;
            const float4 b = __ldg(reinterpret_cast<const float4*>(bias + col));
            float x = b.x, y = b.y, z = b.z, w = b.w;
            const float* base = g_scratch + (size_t)row * NN + col;
#pragma unroll
            for (int sp2 = 0; sp2 < K_SPLIT; sp2++) {
                const float4 v = *reinterpret_cast<const float4*>(base + (size_t)sp2 * (MM * NN));
                x += v.x; y += v.y; z += v.z; w += v.w;
            }
            *reinterpret_cast<float4*>(out + (size_t)row * NN + col) = make_float4(x, y, z, w);
        }
    }
}

extern "C" void kernel_launch(void* const* d_in, const int* in_sizes, int n_in,
                              void* d_out, int out_size) {
    const float* A       = (const float*)d_in[0];
    const int*   qweight = (const int*)  d_in[1];
    const float* scales  = (const float*)d_in[2];
    const float* bias    = (const float*)d_in[3];
    float*       out     = (float*)d_out;

    dim3 grid(NTILES, K_SPLIT);
    marlin_fused_kernel<<<grid, THREADS>>>(A, qweight, scales, bias, out);
}

// round 9
// speedup vs baseline: 1.0645x; 1.0645x over previous
#include <cuda_runtime.h>
#include <cuda_fp16.h>
#include <cstdint>

// Problem constants
#define MM 32
#define KK 8192
#define NN 8192
#define GROUP 128

// Tiling
#define K_SPLIT 8
#define K_CHUNK (KK / K_SPLIT)           // 1024
#define GROUPS_PER_CTA (K_CHUNK / GROUP) // 8
#define WARPS 4
#define THREADS 128
#define WARP_N 32
#define N_TILE (WARPS * WARP_N)          // 128
#define NTILES (NN / N_TILE)             // 64
#define ASTRIDE 136                      // fp16 elems per SMEM A row (128 + 8 pad)

// Deterministic K-split partials + arrival counters (no alloc)
__device__ __align__(16) float  g_scratch[K_SPLIT * MM * NN]; // 8 MB
__device__ unsigned int g_cnt[NTILES];                        // zero-init; reset by last CTA

// ---------------- PTX helpers ----------------
__device__ __forceinline__ void ldsm_x4(uint32_t addr, uint32_t* r) {
    asm volatile("ldmatrix.sync.aligned.m8n8.x4.shared.b16 {%0,%1,%2,%3}, [%4];"
                 : "=r"(r[0]), "=r"(r[1]), "=r"(r[2]), "=r"(r[3]) : "r"(addr));
}
__device__ __forceinline__ void lds128(uint32_t addr, uint32_t* r) {
    asm volatile("ld.shared.v4.u32 {%0,%1,%2,%3}, [%4];"
                 : "=r"(r[0]), "=r"(r[1]), "=r"(r[2]), "=r"(r[3]) : "r"(addr));
}
__device__ __forceinline__ void mma16816(float* c, const uint32_t* a, uint32_t b0, uint32_t b1) {
    asm volatile("mma.sync.aligned.m16n8k16.row.col.f32.f16.f16.f32 "
                 "{%0,%1,%2,%3}, {%4,%5,%6,%7}, {%8,%9}, {%0,%1,%2,%3};"
                 : "+f"(c[0]), "+f"(c[1]), "+f"(c[2]), "+f"(c[3])
                 : "r"(a[0]), "r"(a[1]), "r"(a[2]), "r"(a[3]), "r"(b0), "r"(b1));
}

// k-interleaved dequant: lane lr uses nibbles (lr, lr+4) of word w.
// v = w >> (4*lr): nibble lr at bits[3:0], nibble lr+4 at bits[19:16].
// (v & 0x000F000F) | 0x64006400 = fp16x2(1024+q_lo, 1024+q_hi); subtract 1032 -> exact (q-8).
// Then scale by s (fp16x2 broadcast).
__device__ __forceinline__ uint32_t dqs(uint32_t w, int sh, uint32_t s2) {
    uint32_t t = ((w >> sh) & 0x000F000Fu) | 0x64006400u;  // SHF + 1 LOP3
    __half2 x = *reinterpret_cast<__half2*>(&t);
    const __half2 c = __half2half2(__ushort_as_half(0x6408)); // 1032.0 (exact)
    __half2 y = __hmul2(__hsub2(x, c), *reinterpret_cast<__half2*>(&s2));
    return *reinterpret_cast<uint32_t*>(&y);
}

__device__ __forceinline__ void cp4(uint32_t saddr, const void* gptr) {
    asm volatile("cp.async.ca.shared.global [%0], [%1], 4;" :: "r"(saddr), "l"(gptr));
}
__device__ __forceinline__ void cp_commit() {
    asm volatile("cp.async.commit_group;");
}
template <int N>
__device__ __forceinline__ void cp_wait() {
    asm volatile("cp.async.wait_group %0;" :: "n"(N));
}

// ---------------- Fused GEMM (A-convert in registers + mma + split-K reduce) ----------------
// sa16: double-buffered fp16 A group tile [32 x ASTRIDE], k-interleaved per 8-granule
// sq:   double-buffered permuted qweight tiles; per buffer off = ks*256 + warp*64 + lq*8 + rl*4 + nf
__global__ void __launch_bounds__(THREADS, 4)
marlin_fused_kernel(const float* __restrict__ A,
                    const int*   __restrict__ qweight,
                    const float* __restrict__ scales,
                    const float* __restrict__ bias,
                    float*       __restrict__ out) {
    __shared__ __align__(16) __half sa16[2][MM * ASTRIDE];  // 2 x 8704 B
    __shared__ __align__(16) int    sq[2][2048];            // 2 x 8192 B
    __shared__ unsigned int s_last;

    const int tid  = threadIdx.x;
    const int warp = tid >> 5;
    const int lane = tid & 31;
    const int lq   = lane >> 2;   // 0..7
    const int lr   = lane & 3;    // 0..3
    const int shq  = lr << 2;     // nibble shift for dequant

    const int nb_cta = blockIdx.x * N_TILE;
    const int nb     = nb_cta + warp * WARP_N;
    const int kbase  = blockIdx.y * K_CHUNK;

    const int lm_row = lane & 15;
    const int lm_k   = (lane >> 4) << 3;

    const uint32_t sa_base = (uint32_t)__cvta_generic_to_shared(&sa16[0][0]);
    const uint32_t sq_base = (uint32_t)__cvta_generic_to_shared(&sq[0][0]);

    // Permuted qweight destination offset (tid = CTA column c):
    const int perm_c = ((tid >> 5) << 6) | ((tid & 7) << 3) | ((tid >> 3) & 3);

    // ---- A group load into registers (4 granules of 8 k per thread) ----
    float4 av[8];
    auto ldA = [&](int gk) {
#pragma unroll
        for (int j = 0; j < 4; j++) {
            const int gi  = j * THREADS + tid;      // granule 0..511
            const int row = gi >> 4, gc = gi & 15;  // 32 rows x 16 granules
            const float* p = A + (size_t)row * KK + gk + gc * 8;
            av[2 * j]     = __ldg(reinterpret_cast<const float4*>(p));
            av[2 * j + 1] = __ldg(reinterpret_cast<const float4*>(p + 4));
        }
    };
    // ---- convert + store registers -> sa16[buf], k-interleaved within each granule ----
    auto stA = [&](int buf) {
        __half* base = &sa16[buf][0];
#pragma unroll
        for (int j = 0; j < 4; j++) {
            const int gi  = j * THREADS + tid;
            const int row = gi >> 4, gc = gi & 15;
            const float4 a = av[2 * j], b = av[2 * j + 1];
            __half2 h0 = __floats2half2_rn(a.x, b.x);  // slots 0,1 = phys k0,k4
            __half2 h1 = __floats2half2_rn(a.y, b.y);  // slots 2,3 = phys k1,k5
            __half2 h2 = __floats2half2_rn(a.z, b.z);  // slots 4,5 = phys k2,k6
            __half2 h3 = __floats2half2_rn(a.w, b.w);  // slots 6,7 = phys k3,k7
            uint4 o;
            o.x = *reinterpret_cast<uint32_t*>(&h0);
            o.y = *reinterpret_cast<uint32_t*>(&h1);
            o.z = *reinterpret_cast<uint32_t*>(&h2);
            o.w = *reinterpret_cast<uint32_t*>(&h3);
            *reinterpret_cast<uint4*>(&base[row * ASTRIDE + gc * 8]) = o;
        }
    };
    // ---- async stage of one group's permuted qweight tile ----
    auto stage_q = [&](int buf, int gk) {
        const uint32_t sq_b = sq_base + (uint32_t)buf * (2048 * 4);
        const int kp_g = gk >> 3;
        const int* qsrc = qweight + (size_t)kp_g * NN + nb_cta + tid;
#pragma unroll
        for (int r = 0; r < 16; r++) {
            const int ks = r >> 1, rl = r & 1;
            const int off = ks * 256 + perm_c + rl * 4;
            cp4(sq_b + (uint32_t)off * 4, qsrc + (size_t)r * NN);
        }
    };

    float acc[32];
#pragma unroll
    for (int i = 0; i < 32; i++) acc[i] = 0.f;

    // Prologue: A(0) -> buf0; q(0) committed; A(1) in flight in registers.
    ldA(kbase);
    stA(0);
    stage_q(0, kbase);
    cp_commit();
    ldA(kbase + GROUP);

    for (int g = 0; g < GROUPS_PER_CTA; g++) {
        const int gk = kbase + g * GROUP;
        cp_wait<0>();      // q(g) arrived (committed one mma-loop ago)
        __syncthreads();   // sa16[g&1] stores + sq[g&1] visible; old-buffer reads done

        if (g + 1 < GROUPS_PER_CTA) {
            stage_q((g + 1) & 1, gk + GROUP);  // flies under mma(g)
            cp_commit();
        }

        // fp16 scales for this group's B columns (n = nb + nf*8 + lq)
        const float* sp = scales + (size_t)(gk >> 7) * NN + nb + lq;
        uint32_t s2[4];
#pragma unroll
        for (int nf = 0; nf < 4; nf++) {
            const __half2 h = __float2half2_rn(__ldg(sp + nf * 8));
            s2[nf] = *reinterpret_cast<const uint32_t*>(&h);
        }

        const uint32_t sa_b = sa_base + (uint32_t)(g & 1) * (MM * ASTRIDE * 2);
        const uint32_t sq_b = sq_base + (uint32_t)(g & 1) * (2048 * 4)
                            + (uint32_t)(warp * 64 + lq * 8) * 4;

#pragma unroll
        for (int ks = 0; ks < 8; ks++) {
            uint32_t a0[4], a1[4];
            const int kcol = (ks << 4) + lm_k;
            ldsm_x4(sa_b + (uint32_t)(lm_row * ASTRIDE + kcol) * 2, a0);
            ldsm_x4(sa_b + (uint32_t)((16 + lm_row) * ASTRIDE + kcol) * 2, a1);

            uint32_t q[8];
            const uint32_t qaddr = sq_b + (uint32_t)(ks * 256) * 4;
            lds128(qaddr, q);          // word 2ks   (k 0-7),  nf 0..3
            lds128(qaddr + 16, q + 4); // word 2ks+1 (k 8-15), nf 0..3

#pragma unroll
            for (int nf = 0; nf < 4; nf++) {
                const uint32_t b0 = dqs(q[nf],     shq, s2[nf]);
                const uint32_t b1 = dqs(q[4 + nf], shq, s2[nf]);
                mma16816(acc + nf * 8,     a0, b0, b1);
                mma16816(acc + nf * 8 + 4, a1, b0, b1);
            }
        }

        // Stage A for next group; start LDGs for group after that.
        if (g + 1 < GROUPS_PER_CTA) {
            stA((g + 1) & 1);
            if (g + 2 < GROUPS_PER_CTA) ldA(gk + 2 * GROUP);
        }
    }

    // ---- Deterministic K-split partials ----
    float* dst = g_scratch + (size_t)blockIdx.y * (MM * NN);
#pragma unroll
    for (int nf = 0; nf < 4; nf++) {
#pragma unroll
        for (int mt = 0; mt < 2; mt++) {
            const float* c = acc + nf * 8 + mt * 4;
            const int col  = nb + nf * 8 + (lr << 1);
            const int row0 = mt * 16 + lq;
            *reinterpret_cast<float2*>(dst + (size_t)row0 * NN + col)       = make_float2(c[0], c[1]);
            *reinterpret_cast<float2*>(dst + (size_t)(row0 + 8) * NN + col) = make_float2(c[2], c[3]);
        }
    }

    // ---- Fused split-K reduction: last-arriving CTA of this n-tile finishes ----
    __threadfence();       // partials visible before the arrival tick
    __syncthreads();       // all threads' stores issued before tid0 ticks
    if (tid == 0) {
        const unsigned old = atomicAdd(&g_cnt[blockIdx.x], 1u);
        if (old == K_SPLIT - 1) {
            g_cnt[blockIdx.x] = 0;   // reset for next launch (graph replay safe)
            s_last = 1u;
        } else {
            s_last = 0u;
        }
    }
    __syncthreads();

    if (s_last) {
        __threadfence();   // acquire: see all other CTAs' partials
#pragma unroll
        for (int it = 0; it < 8; it++) {
            const int f   = it * THREADS + tid;     // float4 index within tile
            const int row = f >> 5, c4 = f & 31;
            const int col = nb_cta + c4 * 4;
            const float4 b = __ldg(reinterpret_cast<const float4*>(bias + col));
            float x = b.x, y = b.y, z = b.z, w = b.w;
            const float* base = g_scratch + (size_t)row * NN + col;
#pragma unroll
            for (int sp2 = 0; sp2 < K_SPLIT; sp2++) {
                const float4 v = *reinterpret_cast<const float4*>(base + (size_t)sp2 * (MM * NN));
                x += v.x; y += v.y; z += v.z; w += v.w;
            }
            *reinterpret_cast<float4*>(out + (size_t)row * NN + col) = make_float4(x, y, z, w);
        }
    }
}

extern "C" void kernel_launch(void* const* d_in, const int* in_sizes, int n_in,
                              void* d_out, int out_size) {
    const float* A       = (const float*)d_in[0];
    const int*   qweight = (const int*)  d_in[1];
    const float* scales  = (const float*)d_in[2];
    const float* bias    = (const float*)d_in[3];
    float*       out     = (float*)d_out;

    dim3 grid(NTILES, K_SPLIT);
    marlin_fused_kernel<<<grid, THREADS>>>(A, qweight, scales, bias, out);
}